// round 12
// baseline (speedup 1.0000x reference)
#include <cuda_runtime.h>

#define BN   256
#define RN   2048
#define NCAP 10
#define OD   16
#define IND  8
#define NO   (NCAP * OD)   // 160

// 335 MB scratch for u_hat[b][r][o], o = n*16 + d in [0,160)
__device__ float g_uhat[(size_t)BN * RN * NO];

// ---------------------------------------------------------------------------
// Kernel 1: u_hat[b,r,o] = sum_i x[b,r,i] * W[r,i,o]
// One CTA per r. Each lane keeps its 8x5 slice of W[r] in registers and
// reuses it across all 256 batch rows. x broadcast via shfl.
// ---------------------------------------------------------------------------
__global__ void __launch_bounds__(512)
uhat_kernel(const float* __restrict__ x,
            const float* __restrict__ W) {
    const int r    = blockIdx.x;
    const int lane = threadIdx.x & 31;
    const int warp = threadIdx.x >> 5;
    const int nw   = blockDim.x >> 5;

    float wreg[IND][5];
#pragma unroll
    for (int i = 0; i < IND; ++i)
#pragma unroll
        for (int k = 0; k < 5; ++k)
            wreg[i][k] = W[((size_t)r * IND + i) * NO + lane + 32 * k];

    for (int b = warp; b < BN; b += nw) {
        float xv = 0.0f;
        if (lane < IND) xv = x[((size_t)b * RN + r) * IND + lane];

        float u[5] = {0.f, 0.f, 0.f, 0.f, 0.f};
#pragma unroll
        for (int i = 0; i < IND; ++i) {
            float xi = __shfl_sync(0xffffffffu, xv, i);
#pragma unroll
            for (int k = 0; k < 5; ++k)
                u[k] = fmaf(xi, wreg[i][k], u[k]);
        }
        size_t base = ((size_t)b * RN + r) * (size_t)NO + lane;
#pragma unroll
        for (int k = 0; k < 5; ++k)
            __stcs(&g_uhat[base + 32 * k], u[k]);
    }
}

// ---------------------------------------------------------------------------
// Kernel 2: dynamic routing, one batch element per CTA, TWO ROWS PER WARP
// (one per half-warp). Lane (h = lane>>4, j = lane&15) owns, for its row,
// u[row, capsule k, d=j] for k = 0..9 (10 registers).
//   - agreement dot over d: xor-8/xor-4 tree + 4-way atomicAdd into bB
//   - softmax over 10 capsules: per-half 4-level xor trees (serves 2 rows
//     per instruction)
//   - s accumulation: per-lane (n=k, d=j) accumulators, merged via smem
// ---------------------------------------------------------------------------
__global__ void __launch_bounds__(512, 2)
route_kernel(const float* __restrict__ blog,
             const float* __restrict__ uhat_g,
             float* __restrict__ outv,
             float* __restrict__ outc) {
    extern __shared__ float sm[];
    float* bB       = sm;                 // RN*NCAP = 20480 floats
    float* s_sh     = bB + RN * NCAP;     // 160
    float* vsh      = s_sh + NO;          // 160
    float* scale_sh = vsh + NO;           // 16

    const int b    = blockIdx.x;
    const int tid  = threadIdx.x;
    const int lane = tid & 31;
    const int warp = tid >> 5;
    const int nw   = blockDim.x >> 5;     // 16
    const int j    = lane & 15;           // lane within half
    const int srcBase = lane & 16;        // shfl source base for this half

    for (int i = tid; i < RN * NCAP; i += blockDim.x) bB[i] = blog[i];
    if (tid < NO) s_sh[tid] = 0.0f;
    __syncthreads();

    float vreg[NCAP], sAcc[NCAP];
#pragma unroll
    for (int k = 0; k < NCAP; ++k) { vreg[k] = 0.0f; sAcc[k] = 0.0f; }

    const float* uh    = uhat_g + (size_t)b * RN * NO;
    const int    rstep = 2 * nw;          // 32 rows per step across the CTA
    const int    steps = RN / rstep;      // 64

    for (int iter = 0; iter <= 3; ++iter) {
        const bool agree = (iter > 0);
        const bool wC    = (iter == 3);

        int r = 2 * warp + (lane >> 4);   // this lane's row
        float u[NCAP];
        {
            const float* p = uh + (size_t)r * NO + j;
#pragma unroll
            for (int k = 0; k < NCAP; ++k) u[k] = __ldcs(&p[OD * k]);
        }

        for (int t = 0; t < steps; ++t) {
            const int rn = r + rstep;
            float un[NCAP];
            if (t + 1 < steps) {          // prefetch next row's u_hat
                const float* p = uh + (size_t)rn * NO + j;
#pragma unroll
                for (int k = 0; k < NCAP; ++k) un[k] = __ldcs(&p[OD * k]);
            } else {
#pragma unroll
                for (int k = 0; k < NCAP; ++k) un[k] = 0.0f;
            }

            if (agree) {
                // a[k] = sum_d u[r,k,d]*v[k,d]; 2-level tree + quad atomics
#pragma unroll
                for (int k = 0; k < NCAP; ++k) {
                    float p = u[k] * vreg[k];
                    p += __shfl_xor_sync(0xffffffffu, p, 8);
                    p += __shfl_xor_sync(0xffffffffu, p, 4);
                    if ((lane & 12) == 0)
                        atomicAdd(&bB[r * NCAP + k], p);
                }
                __syncwarp();
            }

            // softmax over 10 capsules — per-half, both rows simultaneously
            float val = (j < NCAP) ? bB[r * NCAP + j] : -1e30f;
            float m = val;
            m = fmaxf(m, __shfl_xor_sync(0xffffffffu, m, 8));
            m = fmaxf(m, __shfl_xor_sync(0xffffffffu, m, 4));
            m = fmaxf(m, __shfl_xor_sync(0xffffffffu, m, 2));
            m = fmaxf(m, __shfl_xor_sync(0xffffffffu, m, 1));
            float e = (j < NCAP) ? __expf(val - m) : 0.0f;
            float ss = e;
            ss += __shfl_xor_sync(0xffffffffu, ss, 8);
            ss += __shfl_xor_sync(0xffffffffu, ss, 4);
            ss += __shfl_xor_sync(0xffffffffu, ss, 2);
            ss += __shfl_xor_sync(0xffffffffu, ss, 1);
            float c = e * __frcp_rn(ss);  // valid on lanes with j<10

            if (wC && outc != nullptr && j < NCAP)
                outc[((size_t)b * RN + r) * NCAP + j] = c;

            // s accumulation: sAcc[k] += c[k] * u[r,k,j]
#pragma unroll
            for (int k = 0; k < NCAP; ++k) {
                float ck = __shfl_sync(0xffffffffu, c, srcBase + k);
                sAcc[k] = fmaf(ck, u[k], sAcc[k]);
            }

#pragma unroll
            for (int k = 0; k < NCAP; ++k) u[k] = un[k];
            r = rn;
        }

        // merge per-lane s partials: lane (h,j) holds (n=k, d=j) pieces
#pragma unroll
        for (int k = 0; k < NCAP; ++k)
            atomicAdd(&s_sh[k * OD + j], sAcc[k]);
        __syncthreads();

        if (tid < NCAP) {
            float n2 = 0.0f;
#pragma unroll
            for (int d = 0; d < OD; ++d) {
                float sv = s_sh[tid * OD + d];
                n2 = fmaf(sv, sv, n2);
            }
            scale_sh[tid] = sqrtf(n2) / (1.0f + n2 + 1e-8f);
        }
        __syncthreads();
        if (tid < NO) vsh[tid] = scale_sh[tid >> 4] * s_sh[tid];
        __syncthreads();
#pragma unroll
        for (int k = 0; k < NCAP; ++k) {
            vreg[k] = vsh[k * OD + j];
            sAcc[k] = 0.0f;
        }
        if (tid < NO) s_sh[tid] = 0.0f;
        __syncthreads();
    }

    // final v (output order: v first, then c)
    if (tid < NO) outv[(size_t)b * NO + tid] = vsh[tid];
}

// ---------------------------------------------------------------------------
extern "C" void kernel_launch(void* const* d_in, const int* in_sizes, int n_in,
                              void* d_out, int out_size) {
    const float* x    = (const float*)d_in[0];   // [256, 2048, 8]
    const float* W    = (const float*)d_in[1];   // [2048, 8, 160]
    const float* blog = (const float*)d_in[2];   // [2048, 10]

    float* out  = (float*)d_out;
    float* outv = out;                            // v: [256, 10, 16]
    float* outc = nullptr;                        // c: [256, 2048, 10]
    const long long vElems = (long long)BN * NO;
    const long long cElems = (long long)BN * RN * NCAP;
    if ((long long)out_size >= vElems + cElems) outc = out + vElems;

    uhat_kernel<<<RN, 512>>>(x, W);

    const size_t smem = (size_t)(RN * NCAP + 2 * NO + 16) * sizeof(float); // 83264 B
    cudaFuncSetAttribute(route_kernel,
                         cudaFuncAttributeMaxDynamicSharedMemorySize,
                         (int)smem);
    void* uhat_ptr = nullptr;
    cudaGetSymbolAddress(&uhat_ptr, g_uhat);
    route_kernel<<<BN, 512, smem>>>(blog, (const float*)uhat_ptr, outv, outc);
}

// round 16
// speedup vs baseline: 1.4781x; 1.4781x over previous
#include <cuda_runtime.h>

#define BN   256
#define RN   2048
#define NCAP 10
#define OD   16
#define IND  8
#define NO   (NCAP * OD)   // 160

// 335 MB scratch for u_hat[b][r][o], o = n*16 + d in [0,160)
__device__ float g_uhat[(size_t)BN * RN * NO];
// batch-independent initial coupling c0 = softmax(blog), [2048][10]
__device__ float g_c0[RN * NCAP];

// ---------------------------------------------------------------------------
// Kernel 0: c0[r,n] = softmax(blog[r,:])[n]   (batch-independent, ~3us)
// ---------------------------------------------------------------------------
__global__ void c0_kernel(const float* __restrict__ blog) {
    int r = blockIdx.x * blockDim.x + threadIdx.x;
    if (r >= RN) return;
    float v[NCAP];
    float m = -1e30f;
#pragma unroll
    for (int n = 0; n < NCAP; ++n) { v[n] = blog[r * NCAP + n]; m = fmaxf(m, v[n]); }
    float s = 0.0f;
#pragma unroll
    for (int n = 0; n < NCAP; ++n) { v[n] = __expf(v[n] - m); s += v[n]; }
    float inv = __frcp_rn(s);
#pragma unroll
    for (int n = 0; n < NCAP; ++n) g_c0[r * NCAP + n] = v[n] * inv;
}

// ---------------------------------------------------------------------------
// Kernel 1: u_hat[b,r,o] = sum_i x[b,r,i] * W[r,i,o]
// One CTA per r. Each lane keeps its 8x5 slice of W[r] in registers and
// reuses it across all 256 batch rows. x broadcast via shfl.
// ---------------------------------------------------------------------------
__global__ void __launch_bounds__(512)
uhat_kernel(const float* __restrict__ x,
            const float* __restrict__ W) {
    const int r    = blockIdx.x;
    const int lane = threadIdx.x & 31;
    const int warp = threadIdx.x >> 5;
    const int nw   = blockDim.x >> 5;

    float wreg[IND][5];
#pragma unroll
    for (int i = 0; i < IND; ++i)
#pragma unroll
        for (int k = 0; k < 5; ++k)
            wreg[i][k] = W[((size_t)r * IND + i) * NO + lane + 32 * k];

    for (int b = warp; b < BN; b += nw) {
        float xv = 0.0f;
        if (lane < IND) xv = x[((size_t)b * RN + r) * IND + lane];

        float u[5] = {0.f, 0.f, 0.f, 0.f, 0.f};
#pragma unroll
        for (int i = 0; i < IND; ++i) {
            float xi = __shfl_sync(0xffffffffu, xv, i);
#pragma unroll
            for (int k = 0; k < 5; ++k)
                u[k] = fmaf(xi, wreg[i][k], u[k]);
        }
        size_t base = ((size_t)b * RN + r) * (size_t)NO + lane;
#pragma unroll
        for (int k = 0; k < 5; ++k)
            __stcs(&g_uhat[base + 32 * k], u[k]);
    }
}

// ---------------------------------------------------------------------------
// Kernel 2: dynamic routing, one batch element per CTA (R11 layout).
// Lane owns o = lane + 32k (k = 0..4); capsule n(o) = 2k + (lane>>4).
//   Pass 0: s = sum_r c0[r]*u_hat[r]  (c0 precomputed, no softmax here)
//   Passes 1..3: bB += dot(u,v); c = softmax(bB); s accumulate; squash.
// Softmax / agreement trees are 4-level (within 16-lane halves) — the
// xor-16 level is dead work since valid lanes are 0..9 / per-half.
// ---------------------------------------------------------------------------
__global__ void __launch_bounds__(512)
route_kernel(const float* __restrict__ blog,
             const float* __restrict__ uhat_g,
             const float* __restrict__ c0g,
             float* __restrict__ outv,
             float* __restrict__ outc) {
    extern __shared__ float sm[];
    float* bB       = sm;                 // RN*NCAP = 20480 floats
    float* s_sh     = bB + RN * NCAP;     // 160
    float* vsh      = s_sh + NO;          // 160
    float* scale_sh = vsh + NO;           // 16

    const int b    = blockIdx.x;
    const int tid  = threadIdx.x;
    const int lane = tid & 31;
    const int warp = tid >> 5;
    const int nw   = blockDim.x >> 5;     // 16
    const int half = lane >> 4;           // 0 / 1

    for (int i = tid; i < RN * NCAP; i += blockDim.x) bB[i] = blog[i];
    if (tid < NO) s_sh[tid] = 0.0f;
    __syncthreads();

    float vreg[5], sAcc[5];
#pragma unroll
    for (int k = 0; k < 5; ++k) { vreg[k] = 0.0f; sAcc[k] = 0.0f; }

    const float* uh   = uhat_g + (size_t)b * RN * NO;
    const int   tasks = RN / nw;          // 128

    for (int iter = 0; iter <= 3; ++iter) {
        const bool agree = (iter > 0);
        const bool wC    = (iter == 3);

        int r = warp;
        float u[5];
        {
            const float* p = uh + (size_t)r * NO + lane;
#pragma unroll
            for (int k = 0; k < 5; ++k) u[k] = __ldcs(&p[32 * k]);
        }

        for (int t = 0; t < tasks; ++t) {
            const int rn = r + nw;
            float un[5];
            if (t + 1 < tasks) {               // prefetch next row's u_hat
                const float* p = uh + (size_t)rn * NO + lane;
#pragma unroll
                for (int k = 0; k < 5; ++k) un[k] = __ldcs(&p[32 * k]);
            } else {
#pragma unroll
                for (int k = 0; k < 5; ++k) un[k] = 0.0f;
            }

            if (!agree) {
                // pass 0: c is the precomputed softmax(blog) — just accumulate
#pragma unroll
                for (int k = 0; k < 5; ++k) {
                    float ck = __ldg(&c0g[r * NCAP + 2 * k + half]);
                    sAcc[k] = fmaf(ck, u[k], sAcc[k]);
                }
            } else {
                // agreement a[n] = sum over 16 d's of u*v; 4-level xor tree
                // per half (broadcast within half), lanes 0/16 commit to bB
#pragma unroll
                for (int k = 0; k < 5; ++k) {
                    float p = u[k] * vreg[k];
                    p += __shfl_xor_sync(0xffffffffu, p, 8);
                    p += __shfl_xor_sync(0xffffffffu, p, 4);
                    p += __shfl_xor_sync(0xffffffffu, p, 2);
                    p += __shfl_xor_sync(0xffffffffu, p, 1);
                    if (lane == 0 || lane == 16)
                        bB[r * NCAP + 2 * k + half] += p;
                }
                __syncwarp();

                // softmax over the 10 capsule classes (lanes 0..9 valid;
                // 4-level tree stays within the 16-lane half)
                float val = (lane < NCAP) ? bB[r * NCAP + lane] : -1e30f;
                float m = val;
                m = fmaxf(m, __shfl_xor_sync(0xffffffffu, m, 8));
                m = fmaxf(m, __shfl_xor_sync(0xffffffffu, m, 4));
                m = fmaxf(m, __shfl_xor_sync(0xffffffffu, m, 2));
                m = fmaxf(m, __shfl_xor_sync(0xffffffffu, m, 1));
                float e = (lane < NCAP) ? __expf(val - m) : 0.0f;
                float ssum = e;
                ssum += __shfl_xor_sync(0xffffffffu, ssum, 8);
                ssum += __shfl_xor_sync(0xffffffffu, ssum, 4);
                ssum += __shfl_xor_sync(0xffffffffu, ssum, 2);
                ssum += __shfl_xor_sync(0xffffffffu, ssum, 1);
                float c = e * __frcp_rn(ssum);   // valid on lanes 0..9

                if (wC && outc != nullptr && lane < NCAP)
                    outc[((size_t)b * RN + r) * NCAP + lane] = c;

                // s accumulation: sAcc[k] += c[n(o)] * u[o]
                // (shfl sources 2k+half are lanes 0..9 — always valid c)
#pragma unroll
                for (int k = 0; k < 5; ++k) {
                    float ck = __shfl_sync(0xffffffffu, c, 2 * k + half);
                    sAcc[k] = fmaf(ck, u[k], sAcc[k]);
                }
            }

#pragma unroll
            for (int k = 0; k < 5; ++k) u[k] = un[k];
            r = rn;
        }

        // cross-warp reduction of s, then squash -> v
#pragma unroll
        for (int k = 0; k < 5; ++k)
            atomicAdd(&s_sh[lane + 32 * k], sAcc[k]);
        __syncthreads();

        if (tid < NCAP) {
            float n2 = 0.0f;
#pragma unroll
            for (int d = 0; d < OD; ++d) {
                float sv = s_sh[tid * OD + d];
                n2 = fmaf(sv, sv, n2);
            }
            scale_sh[tid] = sqrtf(n2) / (1.0f + n2 + 1e-8f);
        }
        __syncthreads();
        if (tid < NO) vsh[tid] = scale_sh[tid >> 4] * s_sh[tid];
        __syncthreads();
#pragma unroll
        for (int k = 0; k < 5; ++k) {
            vreg[k] = vsh[lane + 32 * k];
            sAcc[k] = 0.0f;
        }
        if (tid < NO) s_sh[tid] = 0.0f;
        __syncthreads();
    }

    // final v (output order: v first, then c)
    if (tid < NO) outv[(size_t)b * NO + tid] = vsh[tid];
}

// ---------------------------------------------------------------------------
extern "C" void kernel_launch(void* const* d_in, const int* in_sizes, int n_in,
                              void* d_out, int out_size) {
    const float* x    = (const float*)d_in[0];   // [256, 2048, 8]
    const float* W    = (const float*)d_in[1];   // [2048, 8, 160]
    const float* blog = (const float*)d_in[2];   // [2048, 10]

    float* out  = (float*)d_out;
    float* outv = out;                            // v: [256, 10, 16]
    float* outc = nullptr;                        // c: [256, 2048, 10]
    const long long vElems = (long long)BN * NO;
    const long long cElems = (long long)BN * RN * NCAP;
    if ((long long)out_size >= vElems + cElems) outc = out + vElems;

    c0_kernel<<<(RN + 255) / 256, 256>>>(blog);
    uhat_kernel<<<RN, 512>>>(x, W);

    const size_t smem = (size_t)(RN * NCAP + 2 * NO + 16) * sizeof(float); // 83264 B
    cudaFuncSetAttribute(route_kernel,
                         cudaFuncAttributeMaxDynamicSharedMemorySize,
                         (int)smem);
    void* uhat_ptr = nullptr;
    cudaGetSymbolAddress(&uhat_ptr, g_uhat);
    void* c0_ptr = nullptr;
    cudaGetSymbolAddress(&c0_ptr, g_c0);
    route_kernel<<<BN, 512, smem>>>(blog, (const float*)uhat_ptr,
                                    (const float*)c0_ptr, outv, outc);
}

// round 17
// speedup vs baseline: 1.7854x; 1.2079x over previous
#include <cuda_runtime.h>

#define BN   256
#define RN   2048
#define NCAP 10
#define OD   16
#define IND  8
#define NO   (NCAP * OD)   // 160

// 335 MB scratch for u_hat[b][r][o], o = n*16 + d in [0,160)
__device__ float g_uhat[(size_t)BN * RN * NO];
// batch-independent initial coupling c0 = softmax(blog), [2048][10]
__device__ float g_c0[RN * NCAP];

// ---------------------------------------------------------------------------
// Kernel 0: c0[r,n] = softmax(blog[r,:])[n]   (batch-independent, ~6us)
// ---------------------------------------------------------------------------
__global__ void c0_kernel(const float* __restrict__ blog) {
    int r = blockIdx.x * blockDim.x + threadIdx.x;
    if (r >= RN) return;
    float v[NCAP];
    float m = -1e30f;
#pragma unroll
    for (int n = 0; n < NCAP; ++n) { v[n] = blog[r * NCAP + n]; m = fmaxf(m, v[n]); }
    float s = 0.0f;
#pragma unroll
    for (int n = 0; n < NCAP; ++n) { v[n] = __expf(v[n] - m); s += v[n]; }
    float inv = __frcp_rn(s);
#pragma unroll
    for (int n = 0; n < NCAP; ++n) g_c0[r * NCAP + n] = v[n] * inv;
}

// ---------------------------------------------------------------------------
// Kernel 1: u_hat[b,r,o] = sum_i x[b,r,i] * W[r,i,o]
// One CTA per r. Each lane keeps its 8x5 slice of W[r] in registers and
// reuses it across all 256 batch rows. x broadcast via shfl.
// ---------------------------------------------------------------------------
__global__ void __launch_bounds__(512)
uhat_kernel(const float* __restrict__ x,
            const float* __restrict__ W) {
    const int r    = blockIdx.x;
    const int lane = threadIdx.x & 31;
    const int warp = threadIdx.x >> 5;
    const int nw   = blockDim.x >> 5;

    float wreg[IND][5];
#pragma unroll
    for (int i = 0; i < IND; ++i)
#pragma unroll
        for (int k = 0; k < 5; ++k)
            wreg[i][k] = W[((size_t)r * IND + i) * NO + lane + 32 * k];

    for (int b = warp; b < BN; b += nw) {
        float xv = 0.0f;
        if (lane < IND) xv = x[((size_t)b * RN + r) * IND + lane];

        float u[5] = {0.f, 0.f, 0.f, 0.f, 0.f};
#pragma unroll
        for (int i = 0; i < IND; ++i) {
            float xi = __shfl_sync(0xffffffffu, xv, i);
#pragma unroll
            for (int k = 0; k < 5; ++k)
                u[k] = fmaf(xi, wreg[i][k], u[k]);
        }
        size_t base = ((size_t)b * RN + r) * (size_t)NO + lane;
#pragma unroll
        for (int k = 0; k < 5; ++k)
            __stcs(&g_uhat[base + 32 * k], u[k]);
    }
}

// ---------------------------------------------------------------------------
// Kernel 2: dynamic routing, one batch element per CTA.
// Lane owns o = lane + 32k (k = 0..4); capsule n(o) = 2k + half, d = lane&15.
//   Pass 0 (separate loop): s = sum_r c0[r]*u_hat[r]  (c0 precomputed).
//   Passes 1..3: agreement xor-tree broadcasts a[2k+half] to ALL lanes, so
//   each lane holds 5 of the 10 logits in registers -> softmax needs only
//   2 xor-16 shfls (max merge + sum merge) and NO c-broadcast shfls.
// ---------------------------------------------------------------------------
__global__ void __launch_bounds__(512)
route_kernel(const float* __restrict__ blog,
             const float* __restrict__ uhat_g,
             const float* __restrict__ c0g,
             float* __restrict__ outv,
             float* __restrict__ outc) {
    extern __shared__ float sm[];
    float* bB       = sm;                 // RN*NCAP = 20480 floats
    float* s_sh     = bB + RN * NCAP;     // 160
    float* vsh      = s_sh + NO;          // 160
    float* scale_sh = vsh + NO;           // 16

    const int b    = blockIdx.x;
    const int tid  = threadIdx.x;
    const int lane = tid & 31;
    const int warp = tid >> 5;
    const int nw   = blockDim.x >> 5;     // 16
    const int half = lane >> 4;           // 0 / 1
    const bool wrL = (lane == (half << 4));   // lanes 0 and 16

    for (int i = tid; i < RN * NCAP; i += blockDim.x) bB[i] = blog[i];
    if (tid < NO) s_sh[tid] = 0.0f;
    __syncthreads();

    float vreg[5], sAcc[5];
#pragma unroll
    for (int k = 0; k < 5; ++k) { vreg[k] = 0.0f; sAcc[k] = 0.0f; }

    const float* uh   = uhat_g + (size_t)b * RN * NO;
    const int   tasks = RN / nw;          // 128

    // ---------------- Pass 0: s = sum_r c0[r] * u_hat[r] ----------------
    {
        int r = warp;
        float u[5];
        {
            const float* p = uh + (size_t)r * NO + lane;
#pragma unroll
            for (int k = 0; k < 5; ++k) u[k] = __ldcs(&p[32 * k]);
        }
        for (int t = 0; t < tasks; ++t) {
            const int rn = r + nw;
            float un[5];
            if (t + 1 < tasks) {
                const float* p = uh + (size_t)rn * NO + lane;
#pragma unroll
                for (int k = 0; k < 5; ++k) un[k] = __ldcs(&p[32 * k]);
            } else {
#pragma unroll
                for (int k = 0; k < 5; ++k) un[k] = 0.0f;
            }
#pragma unroll
            for (int k = 0; k < 5; ++k) {
                float ck = __ldg(&c0g[r * NCAP + 2 * k + half]);
                sAcc[k] = fmaf(ck, u[k], sAcc[k]);
            }
#pragma unroll
            for (int k = 0; k < 5; ++k) u[k] = un[k];
            r = rn;
        }
        // reduce s, squash -> v
#pragma unroll
        for (int k = 0; k < 5; ++k)
            atomicAdd(&s_sh[lane + 32 * k], sAcc[k]);
        __syncthreads();
        if (tid < NCAP) {
            float n2 = 0.0f;
#pragma unroll
            for (int d = 0; d < OD; ++d) {
                float sv = s_sh[tid * OD + d];
                n2 = fmaf(sv, sv, n2);
            }
            scale_sh[tid] = sqrtf(n2) / (1.0f + n2 + 1e-8f);
        }
        __syncthreads();
        if (tid < NO) vsh[tid] = scale_sh[tid >> 4] * s_sh[tid];
        __syncthreads();
#pragma unroll
        for (int k = 0; k < 5; ++k) {
            vreg[k] = vsh[lane + 32 * k];
            sAcc[k] = 0.0f;
        }
        if (tid < NO) s_sh[tid] = 0.0f;
        __syncthreads();
    }

    // ---------------- Passes 1..3: dynamic routing ----------------
    for (int iter = 1; iter <= 3; ++iter) {
        const bool wC = (iter == 3);

        int r = warp;
        float u[5];
        {
            const float* p = uh + (size_t)r * NO + lane;
#pragma unroll
            for (int k = 0; k < 5; ++k) u[k] = __ldcs(&p[32 * k]);
        }

        for (int t = 0; t < tasks; ++t) {
            const int rn = r + nw;
            float un[5];
            if (t + 1 < tasks) {               // prefetch next row's u_hat
                const float* p = uh + (size_t)rn * NO + lane;
#pragma unroll
                for (int k = 0; k < 5; ++k) un[k] = __ldcs(&p[32 * k]);
            } else {
#pragma unroll
                for (int k = 0; k < 5; ++k) un[k] = 0.0f;
            }

            // agreement + logit update: full xor tree broadcasts a[2k+half]
            // to every lane; add the old bB; lanes 0/16 write back (skipped
            // on the last iter — value is dead after this softmax).
            float lg[5];
#pragma unroll
            for (int k = 0; k < 5; ++k) {
                float p = u[k] * vreg[k];
                p += __shfl_xor_sync(0xffffffffu, p, 8);
                p += __shfl_xor_sync(0xffffffffu, p, 4);
                p += __shfl_xor_sync(0xffffffffu, p, 2);
                p += __shfl_xor_sync(0xffffffffu, p, 1);
                float nl = bB[r * NCAP + 2 * k + half] + p;  // broadcast LDS
                if (!wC && wrL) bB[r * NCAP + 2 * k + half] = nl;
                lg[k] = nl;
            }
            __syncwarp();

            // softmax over 10 capsules from register-resident logits:
            // in-lane reduce over 5, one xor-16 merge for max and for sum
            float mymax = lg[0];
#pragma unroll
            for (int k = 1; k < 5; ++k) mymax = fmaxf(mymax, lg[k]);
            float m = fmaxf(mymax, __shfl_xor_sync(0xffffffffu, mymax, 16));
            float e[5];
            float mysum = 0.0f;
#pragma unroll
            for (int k = 0; k < 5; ++k) { e[k] = __expf(lg[k] - m); mysum += e[k]; }
            float tot = mysum + __shfl_xor_sync(0xffffffffu, mysum, 16);
            float inv = __frcp_rn(tot);

            if (wC && outc != nullptr && wrL) {
                float* oc = outc + ((size_t)b * RN + r) * NCAP + half;
#pragma unroll
                for (int k = 0; k < 5; ++k) oc[2 * k] = e[k] * inv;
            }

            // s accumulation: c_k already lives in this lane
#pragma unroll
            for (int k = 0; k < 5; ++k)
                sAcc[k] = fmaf(e[k] * inv, u[k], sAcc[k]);

#pragma unroll
            for (int k = 0; k < 5; ++k) u[k] = un[k];
            r = rn;
        }

        // cross-warp reduction of s, then squash -> v
#pragma unroll
        for (int k = 0; k < 5; ++k)
            atomicAdd(&s_sh[lane + 32 * k], sAcc[k]);
        __syncthreads();

        if (tid < NCAP) {
            float n2 = 0.0f;
#pragma unroll
            for (int d = 0; d < OD; ++d) {
                float sv = s_sh[tid * OD + d];
                n2 = fmaf(sv, sv, n2);
            }
            scale_sh[tid] = sqrtf(n2) / (1.0f + n2 + 1e-8f);
        }
        __syncthreads();
        if (tid < NO) vsh[tid] = scale_sh[tid >> 4] * s_sh[tid];
        __syncthreads();
#pragma unroll
        for (int k = 0; k < 5; ++k) {
            vreg[k] = vsh[lane + 32 * k];
            sAcc[k] = 0.0f;
        }
        if (tid < NO) s_sh[tid] = 0.0f;
        __syncthreads();
    }

    // final v (output order: v first, then c)
    if (tid < NO) outv[(size_t)b * NO + tid] = vsh[tid];
}

// ---------------------------------------------------------------------------
extern "C" void kernel_launch(void* const* d_in, const int* in_sizes, int n_in,
                              void* d_out, int out_size) {
    const float* x    = (const float*)d_in[0];   // [256, 2048, 8]
    const float* W    = (const float*)d_in[1];   // [2048, 8, 160]
    const float* blog = (const float*)d_in[2];   // [2048, 10]

    float* out  = (float*)d_out;
    float* outv = out;                            // v: [256, 10, 16]
    float* outc = nullptr;                        // c: [256, 2048, 10]
    const long long vElems = (long long)BN * NO;
    const long long cElems = (long long)BN * RN * NCAP;
    if ((long long)out_size >= vElems + cElems) outc = out + vElems;

    c0_kernel<<<(RN + 255) / 256, 256>>>(blog);
    uhat_kernel<<<RN, 512>>>(x, W);

    const size_t smem = (size_t)(RN * NCAP + 2 * NO + 16) * sizeof(float); // 83264 B
    cudaFuncSetAttribute(route_kernel,
                         cudaFuncAttributeMaxDynamicSharedMemorySize,
                         (int)smem);
    void* uhat_ptr = nullptr;
    cudaGetSymbolAddress(&uhat_ptr, g_uhat);
    void* c0_ptr = nullptr;
    cudaGetSymbolAddress(&c0_ptr, g_c0);
    route_kernel<<<BN, 512, smem>>>(blog, (const float*)uhat_ptr,
                                    (const float*)c0_ptr, outv, outc);
}